// round 11
// baseline (speedup 1.0000x reference)
#include <cuda_runtime.h>
#include <math.h>
#include <stdint.h>

#define S_LEN 2048
#define HID   2560
#define NH    32
#define NKV   8
#define HD    128
#define QDIM  (NH*HD)    // 4096
#define KVDIM (NKV*HD)   // 1024

// Scratch (static device arrays; no allocation allowed)
__device__ float g_Q [S_LEN*QDIM];
__device__ float g_K [S_LEN*KVDIM];
__device__ float g_V [S_LEN*KVDIM];
__device__ float g_AO[S_LEN*QDIM];

// ---------------------------------------------------------------------------
// helpers
// ---------------------------------------------------------------------------
__device__ __forceinline__ uint32_t f2tf(float x) {
    uint32_t y;
    asm("cvt.rna.tf32.f32 %0, %1;" : "=r"(y) : "f"(x));
    return y;
}

__device__ __forceinline__ void mma_tf32(float* d, const uint32_t* a, const uint32_t* b) {
    asm volatile(
        "mma.sync.aligned.m16n8k8.row.col.f32.tf32.tf32.f32 "
        "{%0,%1,%2,%3}, {%4,%5,%6,%7}, {%8,%9}, {%0,%1,%2,%3};\n"
        : "+f"(d[0]), "+f"(d[1]), "+f"(d[2]), "+f"(d[3])
        : "r"(a[0]), "r"(a[1]), "r"(a[2]), "r"(a[3]), "r"(b[0]), "r"(b[1]));
}

// ---------------------------------------------------------------------------
// TF32 tensor-core GEMM NT body: C[M,N] = A[M,K] * B[N,K]^T
// BM=128, BN=64, BK=16, 256 threads (8 warps, 4x2), warp tile 32x32.
// Double-buffered smem, one sync per K-tile. ~78 regs -> 3 blocks/SM.
// ---------------------------------------------------------------------------
#define SMS 20  // smem row stride in words

__device__ __forceinline__ void gemm_body64(const float* __restrict__ A,
                                            const float* __restrict__ B,
                                            float* __restrict__ C,
                                            int N, int Kd, int bx, int by,
                                            uint32_t* As, uint32_t* Bs) {
    const int tid  = threadIdx.x;
    const int wid  = tid >> 5;
    const int lane = tid & 31;
    const int wm   = (wid & 3) * 32;   // 4 m-warps
    const int wn   = (wid >> 2) * 32;  // 2 n-warps
    const int g    = lane >> 2;
    const int c    = lane & 3;

    const int sr = tid >> 2;           // 0..63
    const int sc = (tid & 3) * 4;      // 0,4,8,12
    const float* Ap = A + (size_t)(by * 128 + sr) * Kd + sc;
    const float* Bp = B + (size_t)(bx * 64 + sr) * Kd + sc;

    float acc[2][4][4];
#pragma unroll
    for (int i = 0; i < 2; i++)
#pragma unroll
        for (int j = 0; j < 4; j++)
#pragma unroll
            for (int k = 0; k < 4; k++) acc[i][j][k] = 0.f;

    float4 ra0 = *(const float4*)(Ap);
    float4 ra1 = *(const float4*)(Ap + (size_t)64 * Kd);
    float4 rb0 = *(const float4*)(Bp);

    {
        uint4 u;
        u.x = f2tf(ra0.x); u.y = f2tf(ra0.y); u.z = f2tf(ra0.z); u.w = f2tf(ra0.w);
        *(uint4*)&As[sr * SMS + sc] = u;
        u.x = f2tf(ra1.x); u.y = f2tf(ra1.y); u.z = f2tf(ra1.z); u.w = f2tf(ra1.w);
        *(uint4*)&As[(sr + 64) * SMS + sc] = u;
        u.x = f2tf(rb0.x); u.y = f2tf(rb0.y); u.z = f2tf(rb0.z); u.w = f2tf(rb0.w);
        *(uint4*)&Bs[sr * SMS + sc] = u;
    }
    __syncthreads();

    int cur = 0;
    for (int k0 = 0; k0 < Kd; k0 += 16) {
        const bool has_next = (k0 + 16 < Kd);
        if (has_next) {
            ra0 = *(const float4*)(Ap + k0 + 16);
            ra1 = *(const float4*)(Ap + (size_t)64 * Kd + k0 + 16);
            rb0 = *(const float4*)(Bp + k0 + 16);
        }

        const uint32_t* Ab = As + cur * (128 * SMS);
        const uint32_t* Bb = Bs + cur * (64 * SMS);
#pragma unroll
        for (int kk = 0; kk < 16; kk += 8) {
            uint32_t af[2][4], bf[4][2];
#pragma unroll
            for (int mt = 0; mt < 2; mt++) {
                int r0 = wm + mt * 16 + g;
                af[mt][0] = Ab[r0 * SMS + kk + c];
                af[mt][1] = Ab[(r0 + 8) * SMS + kk + c];
                af[mt][2] = Ab[r0 * SMS + kk + c + 4];
                af[mt][3] = Ab[(r0 + 8) * SMS + kk + c + 4];
            }
#pragma unroll
            for (int nt = 0; nt < 4; nt++) {
                int n0 = wn + nt * 8 + g;
                bf[nt][0] = Bb[n0 * SMS + kk + c];
                bf[nt][1] = Bb[n0 * SMS + kk + c + 4];
            }
#pragma unroll
            for (int mt = 0; mt < 2; mt++)
#pragma unroll
                for (int nt = 0; nt < 4; nt++)
                    mma_tf32(acc[mt][nt], af[mt], bf[nt]);
        }

        if (has_next) {
            uint32_t* An = As + (cur ^ 1) * (128 * SMS);
            uint32_t* Bn = Bs + (cur ^ 1) * (64 * SMS);
            uint4 u;
            u.x = f2tf(ra0.x); u.y = f2tf(ra0.y); u.z = f2tf(ra0.z); u.w = f2tf(ra0.w);
            *(uint4*)&An[sr * SMS + sc] = u;
            u.x = f2tf(ra1.x); u.y = f2tf(ra1.y); u.z = f2tf(ra1.z); u.w = f2tf(ra1.w);
            *(uint4*)&An[(sr + 64) * SMS + sc] = u;
            u.x = f2tf(rb0.x); u.y = f2tf(rb0.y); u.z = f2tf(rb0.z); u.w = f2tf(rb0.w);
            *(uint4*)&Bn[sr * SMS + sc] = u;
            __syncthreads();
            cur ^= 1;
        }
    }

#pragma unroll
    for (int mt = 0; mt < 2; mt++) {
#pragma unroll
        for (int nt = 0; nt < 4; nt++) {
            int row = by * 128 + wm + mt * 16 + g;
            int col = bx * 64 + wn + nt * 8 + c * 2;
            float2 v0 = {acc[mt][nt][0], acc[mt][nt][1]};
            float2 v1 = {acc[mt][nt][2], acc[mt][nt][3]};
            *(float2*)(C + (size_t)row * N + col)       = v0;
            *(float2*)(C + (size_t)(row + 8) * N + col) = v1;
        }
    }
}

// Q, K, V projections in ONE flat-grid launch (no dud blocks).
// Q: 1024 blocks (64x16), K: 256 (16x16), V: 256.
__global__ void __launch_bounds__(256, 3) tf32_gemm_qkv(const float* __restrict__ A,
                                                        const float* __restrict__ Bq,
                                                        const float* __restrict__ Bk,
                                                        const float* __restrict__ Bv,
                                                        float* __restrict__ Cq,
                                                        float* __restrict__ Ck,
                                                        float* __restrict__ Cv) {
    __shared__ uint32_t As[2 * 128 * SMS];
    __shared__ uint32_t Bs[2 * 64 * SMS];
    int bid = blockIdx.x;
    const int NXQ = QDIM / 64;    // 64
    const int NXK = KVDIM / 64;   // 16
    const int NQB = NXQ * (S_LEN / 128);  // 1024
    const int NKB = NXK * (S_LEN / 128);  // 256
    if (bid < NQB) {
        gemm_body64(A, Bq, Cq, QDIM, HID, bid % NXQ, bid / NXQ, As, Bs);
    } else if (bid < NQB + NKB) {
        int t = bid - NQB;
        gemm_body64(A, Bk, Ck, KVDIM, HID, t % NXK, t / NXK, As, Bs);
    } else {
        int t = bid - NQB - NKB;
        gemm_body64(A, Bv, Cv, KVDIM, HID, t % NXK, t / NXK, As, Bs);
    }
}

__global__ void __launch_bounds__(256, 3) tf32_gemm_nt(const float* __restrict__ A,
                                                       const float* __restrict__ B,
                                                       float* __restrict__ C,
                                                       int N, int Kd) {
    __shared__ uint32_t As[2 * 128 * SMS];
    __shared__ uint32_t Bs[2 * 64 * SMS];
    gemm_body64(A, B, C, N, Kd, blockIdx.x, blockIdx.y, As, Bs);
}

// ---------------------------------------------------------------------------
// Merged per-head RMSNorm + RoPE over BOTH Q and K, in-place.
// ---------------------------------------------------------------------------
__global__ void rms_rope_all(float* __restrict__ Qx, float* __restrict__ Kx,
                             const float* __restrict__ qw, const float* __restrict__ kw,
                             const float* __restrict__ cosp, const float* __restrict__ sinp) {
    const int NQ = S_LEN * NH;
    int warp = (blockIdx.x * blockDim.x + threadIdx.x) >> 5;
    int lane = threadIdx.x & 31;

    float* p;
    const float* w;
    int s;
    if (warp < NQ) {
        p = Qx + (size_t)warp * HD;
        w = qw;
        s = warp / NH;
    } else {
        int t = warp - NQ;
        p = Kx + (size_t)t * HD;
        w = kw;
        s = t / NKV;
    }

    float4 x = *(float4*)(p + lane * 4);

    float ss = x.x * x.x + x.y * x.y + x.z * x.z + x.w * x.w;
#pragma unroll
    for (int o = 16; o; o >>= 1) ss += __shfl_xor_sync(0xffffffffu, ss, o);
    float r = rsqrtf(ss * (1.0f / HD) + 1e-6f);

    float4 wv = *(const float4*)(w + lane * 4);
    x.x *= r * wv.x; x.y *= r * wv.y; x.z *= r * wv.z; x.w *= r * wv.w;

    float4 rot;
    rot.x = __shfl_xor_sync(0xffffffffu, x.x, 16);
    rot.y = __shfl_xor_sync(0xffffffffu, x.y, 16);
    rot.z = __shfl_xor_sync(0xffffffffu, x.z, 16);
    rot.w = __shfl_xor_sync(0xffffffffu, x.w, 16);
    float sgn = (lane < 16) ? -1.f : 1.f;

    float4 cv = *(const float4*)(cosp + (size_t)s * HD + lane * 4);
    float4 sv = *(const float4*)(sinp + (size_t)s * HD + lane * 4);

    float4 o;
    o.x = x.x * cv.x + sgn * rot.x * sv.x;
    o.y = x.y * cv.y + sgn * rot.y * sv.y;
    o.z = x.z * cv.z + sgn * rot.z * sv.z;
    o.w = x.w * cv.w + sgn * rot.w * sv.w;
    *(float4*)(p + lane * 4) = o;
}

// ---------------------------------------------------------------------------
// Tensor-core causal GQA flash attention (FA-2 style, TF32 mma).
// Block: 256 threads = 8 warps, 128 q rows of one head; warp strip 16 rows.
// K/V tiles of 32 keys; Q kept fp32 in smem, hi/lo split on the fly.
// Smem ~99.5KB -> 2 blocks/SM (16 warps). ~104 regs.
// Fixed-max softmax (RMSNorm bounds scores: s*scale <= 11.33 < 12).
// ---------------------------------------------------------------------------
#define QS_STRIDE 132
#define VS_STRIDE 136

__global__ void __launch_bounds__(256, 2) flash_tc(const float* __restrict__ Q,
                                                   const float* __restrict__ K,
                                                   const float* __restrict__ V,
                                                   float* __restrict__ O) {
    extern __shared__ uint32_t smf[];
    float*    Qs = (float*)smf;                 // [128][132] fp32
    uint32_t* Ks = smf + 128 * QS_STRIDE;       // [32][132] tf32
    uint32_t* Vs = Ks + 32 * QS_STRIDE;         // [32][136] tf32

    const int tid  = threadIdx.x;
    const int w    = tid >> 5;
    const int lane = tid & 31;
    const int g    = lane >> 2;
    const int c    = lane & 3;
    const int h    = blockIdx.y;
    const int kvh  = h >> 2;
    const int base = blockIdx.x * 128;
    const int m0   = w * 16;
    const float scale = 0.08838834764831845f;  // 1/sqrt(128)
    const float FM = 12.0f;

    // stage Q tile (fp32, once per block)
    {
        int r = tid >> 1, half = (tid & 1) * 64;
        const float* src = Q + (size_t)(base + r) * QDIM + h * HD + half;
        float* dst = Qs + r * QS_STRIDE + half;
#pragma unroll
        for (int i = 0; i < 16; i++)
            *(float4*)(dst + i * 4) = *(const float4*)(src + i * 4);
    }

    float oacc[16][4];
#pragma unroll
    for (int i = 0; i < 16; i++) {
        oacc[i][0] = 0.f; oacc[i][1] = 0.f; oacc[i][2] = 0.f; oacc[i][3] = 0.f;
    }
    float lr0 = 0.f, lr1 = 0.f;

    const int row0 = base + m0 + g;
    const int row1 = row0 + 8;
    const int wmax = base + m0 + 15;

    for (int kb = 0; kb <= base + 127; kb += 32) {
        __syncthreads();
        // stage K, V (32 keys, tf32)
        {
            int r = tid >> 3, seg = (tid & 7) * 16;
            const float* ks = K + (size_t)(kb + r) * KVDIM + kvh * HD + seg;
            const float* vs = V + (size_t)(kb + r) * KVDIM + kvh * HD + seg;
            uint32_t* kd = Ks + r * QS_STRIDE + seg;
            uint32_t* vd = Vs + r * VS_STRIDE + seg;
#pragma unroll
            for (int i = 0; i < 4; i++) {
                float4 k4 = *(const float4*)(ks + i * 4);
                uint4 ku = {f2tf(k4.x), f2tf(k4.y), f2tf(k4.z), f2tf(k4.w)};
                *(uint4*)(kd + i * 4) = ku;
                float4 v4 = *(const float4*)(vs + i * 4);
                uint4 vu = {f2tf(v4.x), f2tf(v4.y), f2tf(v4.z), f2tf(v4.w)};
                *(uint4*)(vd + i * 4) = vu;
            }
        }
        __syncthreads();

        if (kb > wmax) continue;   // whole tile causally masked for this warp

        // ---- S = Q @ K^T  (warp strip 16x32), Q hi/lo on the fly ----
        float sacc[4][4];
#pragma unroll
        for (int nt = 0; nt < 4; nt++) {
            sacc[nt][0] = 0.f; sacc[nt][1] = 0.f; sacc[nt][2] = 0.f; sacc[nt][3] = 0.f;
        }
#pragma unroll
        for (int ks8 = 0; ks8 < 16; ks8++) {
            const int kk = ks8 * 8;
            float q0 = Qs[(m0 + g) * QS_STRIDE + kk + c];
            float q1 = Qs[(m0 + 8 + g) * QS_STRIDE + kk + c];
            float q2 = Qs[(m0 + g) * QS_STRIDE + kk + c + 4];
            float q3 = Qs[(m0 + 8 + g) * QS_STRIDE + kk + c + 4];
            uint32_t ahi[4], alo[4];
            ahi[0] = f2tf(q0); alo[0] = f2tf(q0 - __uint_as_float(ahi[0]));
            ahi[1] = f2tf(q1); alo[1] = f2tf(q1 - __uint_as_float(ahi[1]));
            ahi[2] = f2tf(q2); alo[2] = f2tf(q2 - __uint_as_float(ahi[2]));
            ahi[3] = f2tf(q3); alo[3] = f2tf(q3 - __uint_as_float(ahi[3]));
#pragma unroll
            for (int nt = 0; nt < 4; nt++) {
                uint32_t b[2];
                b[0] = Ks[(nt * 8 + g) * QS_STRIDE + kk + c];
                b[1] = Ks[(nt * 8 + g) * QS_STRIDE + kk + c + 4];
                mma_tf32(sacc[nt], alo, b);
                mma_tf32(sacc[nt], ahi, b);
            }
        }

        // ---- softmax (fixed max), convert P to tf32 bits ----
        uint32_t pb[4][4];
#pragma unroll
        for (int nt = 0; nt < 4; nt++) {
            int colb = kb + nt * 8 + 2 * c;
            float p0 = (colb     <= row0) ? __expf(fmaf(sacc[nt][0], scale, -FM)) : 0.f;
            float p1 = (colb + 1 <= row0) ? __expf(fmaf(sacc[nt][1], scale, -FM)) : 0.f;
            float p2 = (colb     <= row1) ? __expf(fmaf(sacc[nt][2], scale, -FM)) : 0.f;
            float p3 = (colb + 1 <= row1) ? __expf(fmaf(sacc[nt][3], scale, -FM)) : 0.f;
            lr0 += p0 + p1;
            lr1 += p2 + p3;
            pb[nt][0] = f2tf(p0); pb[nt][1] = f2tf(p1);
            pb[nt][2] = f2tf(p2); pb[nt][3] = f2tf(p3);
        }

        // ---- O += P @ V ----
        const int src0 = (lane & ~3) | (c >> 1);
        const int src1 = src0 + 2;
#pragma unroll
        for (int kt = 0; kt < 4; kt++) {
            uint32_t x0 = __shfl_sync(0xffffffffu, pb[kt][0], src0);
            uint32_t x1 = __shfl_sync(0xffffffffu, pb[kt][1], src0);
            uint32_t x2 = __shfl_sync(0xffffffffu, pb[kt][2], src0);
            uint32_t x3 = __shfl_sync(0xffffffffu, pb[kt][3], src0);
            uint32_t y0 = __shfl_sync(0xffffffffu, pb[kt][0], src1);
            uint32_t y1 = __shfl_sync(0xffffffffu, pb[kt][1], src1);
            uint32_t y2 = __shfl_sync(0xffffffffu, pb[kt][2], src1);
            uint32_t y3 = __shfl_sync(0xffffffffu, pb[kt][3], src1);
            uint32_t a[4];
            a[0] = (c & 1) ? x1 : x0;   // P(g,   key kt*8+c)
            a[1] = (c & 1) ? x3 : x2;   // P(g+8, key kt*8+c)
            a[2] = (c & 1) ? y1 : y0;   // P(g,   key kt*8+c+4)
            a[3] = (c & 1) ? y3 : y2;   // P(g+8, key kt*8+c+4)
#pragma unroll
            for (int nt = 0; nt < 16; nt++) {
                uint32_t b[2];
                b[0] = Vs[(kt * 8 + c) * VS_STRIDE + nt * 8 + g];
                b[1] = Vs[(kt * 8 + c + 4) * VS_STRIDE + nt * 8 + g];
                mma_tf32(oacc[nt], a, b);
            }
        }
    }

    // ---- epilogue: reduce l across the 4 threads of each row, store ----
    lr0 += __shfl_xor_sync(0xffffffffu, lr0, 1);
    lr0 += __shfl_xor_sync(0xffffffffu, lr0, 2);
    lr1 += __shfl_xor_sync(0xffffffffu, lr1, 1);
    lr1 += __shfl_xor_sync(0xffffffffu, lr1, 2);
    float inv0 = 1.f / lr0;
    float inv1 = 1.f / lr1;

    float* o0 = O + (size_t)row0 * QDIM + h * HD;
    float* o1 = O + (size_t)row1 * QDIM + h * HD;
#pragma unroll
    for (int nt = 0; nt < 16; nt++) {
        int col = nt * 8 + 2 * c;
        float2 v0 = {oacc[nt][0] * inv0, oacc[nt][1] * inv0};
        float2 v1 = {oacc[nt][2] * inv1, oacc[nt][3] * inv1};
        *(float2*)(o0 + col) = v0;
        *(float2*)(o1 + col) = v1;
    }
}

// ---------------------------------------------------------------------------
extern "C" void kernel_launch(void* const* d_in, const int* in_sizes, int n_in,
                              void* d_out, int out_size) {
    const float* X    = (const float*)d_in[0];
    const float* cosp = (const float*)d_in[1];
    const float* sinp = (const float*)d_in[2];
    const float* Wq   = (const float*)d_in[3];
    const float* Wk   = (const float*)d_in[4];
    const float* Wv   = (const float*)d_in[5];
    const float* Wo   = (const float*)d_in[6];
    const float* qw   = (const float*)d_in[7];
    const float* kw   = (const float*)d_in[8];
    float* out = (float*)d_out;

    float *Q, *K, *V, *AO;
    cudaGetSymbolAddress((void**)&Q,  g_Q);
    cudaGetSymbolAddress((void**)&K,  g_K);
    cudaGetSymbolAddress((void**)&V,  g_V);
    cudaGetSymbolAddress((void**)&AO, g_AO);

    // Q + K + V projections, flat grid (1536 blocks, no duds)
    tf32_gemm_qkv<<<1536, 256>>>(X, Wq, Wk, Wv, Q, K, V);

    // RMSNorm + RoPE on Q and K
    {
        int nwarps = S_LEN * NH + S_LEN * NKV;
        rms_rope_all<<<nwarps / 8, 256>>>(Q, K, qw, kw, cosp, sinp);
    }

    // Tensor-core flash attention (8 warps, 128 q-rows/block, 2 blocks/SM)
    int smem = (128 * QS_STRIDE + 32 * QS_STRIDE + 32 * VS_STRIDE) * 4;  // ~101.5KB
    cudaFuncSetAttribute(flash_tc, cudaFuncAttributeMaxDynamicSharedMemorySize, smem);
    flash_tc<<<dim3(S_LEN / 128, NH), 256, smem>>>(Q, K, V, AO);

    // Output projection
    tf32_gemm_nt<<<dim3(HID / 64, S_LEN / 128), 256>>>(AO, Wo, out, HID, QDIM);
}

// round 15
// speedup vs baseline: 1.1131x; 1.1131x over previous
#include <cuda_runtime.h>
#include <cuda_bf16.h>
#include <math.h>
#include <stdint.h>

#define S_LEN 2048
#define HID   2560
#define NH    32
#define NKV   8
#define HD    128
#define QDIM  (NH*HD)    // 4096
#define KVDIM (NKV*HD)   // 1024

// tcgen05 is arch-SPECIFIC (compute_103a only). The harness also builds a
// generic compute_103 PTX pass where tcgen05 does not exist -> guard it.
#if defined(__CUDA_ARCH__) && (defined(__CUDA_ARCH_FEAT_SM103_ALL) || defined(__CUDA_ARCH_FEAT_SM100_ALL))
#define TC5 1
#else
#define TC5 0
#endif

// Scratch (static device arrays; no allocation allowed)
__device__ float g_Q [S_LEN*QDIM];
__device__ float g_K [S_LEN*KVDIM];
__device__ float g_V [S_LEN*KVDIM];
__device__ float g_AO[S_LEN*QDIM];

// ===========================================================================
// common helpers
// ===========================================================================
__device__ __forceinline__ uint32_t f2tf(float x) {
    uint32_t y;
    asm("cvt.rna.tf32.f32 %0, %1;" : "=r"(y) : "f"(x));
    return y;
}

__device__ __forceinline__ void mma_tf32(float* d, const uint32_t* a, const uint32_t* b) {
    asm volatile(
        "mma.sync.aligned.m16n8k8.row.col.f32.tf32.tf32.f32 "
        "{%0,%1,%2,%3}, {%4,%5,%6,%7}, {%8,%9}, {%0,%1,%2,%3};\n"
        : "+f"(d[0]), "+f"(d[1]), "+f"(d[2]), "+f"(d[3])
        : "r"(a[0]), "r"(a[1]), "r"(a[2]), "r"(a[3]), "r"(b[0]), "r"(b[1]));
}

__device__ __forceinline__ uint32_t smem_u32(const void* p) {
    uint32_t a;
    asm("{ .reg .u64 t; cvta.to.shared.u64 t, %1; cvt.u32.u64 %0, t; }" : "=r"(a) : "l"(p));
    return a;
}

// pack two floats -> bf16x2 (first arg -> low 16 bits)
__device__ __forceinline__ uint32_t cvt_bf2(float lo, float hi) {
    uint32_t r;
    asm("cvt.rn.bf16x2.f32 %0, %1, %2;" : "=r"(r) : "f"(hi), "f"(lo));
    return r;
}

#define GSMEM (1024 + 4 * 16384)   // 66560 B for tcgen05 path (covers fallback too)
#define SMS 20                      // fallback smem row stride (words)

#if TC5
// ===========================================================================
// tcgen05 path (sm_103a SASS only)
// ===========================================================================
// SW128 smem descriptor: layout=2(SW128), version=1, SBO=64, LBO=1
__device__ __forceinline__ uint64_t mk_desc(uint32_t addr) {
    const uint64_t base = (uint64_t(2) << 61) | (uint64_t(1) << 46)
                        | (uint64_t(64) << 32) | (uint64_t(1) << 16);
    return base | ((uint64_t)(addr >> 4) & 0x3FFF);
}

__device__ __forceinline__ void mma_f16_ss(uint32_t d, uint64_t da, uint64_t db,
                                           uint32_t idesc, bool en) {
    uint32_t e = en ? 1u : 0u;
    asm volatile(
        "{\n\t.reg .pred p;\n\tsetp.ne.u32 p, %5, 0;\n\t"
        "tcgen05.mma.cta_group::1.kind::f16 [%0], %1, %2, %3, {%4, %4, %4, %4}, p;\n\t}"
        :: "r"(d), "l"(da), "l"(db), "r"(idesc), "r"(0u), "r"(e) : "memory");
}

__device__ __forceinline__ void mbar_wait(uint32_t mbar, uint32_t parity) {
    asm volatile(
        "{\n\t.reg .pred P;\n\t"
        "WL%=:\n\tmbarrier.try_wait.parity.acquire.cta.shared::cta.b64 P, [%0], %1;\n\t"
        "@P bra WD%=;\n\tbra WL%=;\n\tWD%=:\n\t}"
        :: "r"(mbar), "r"(parity) : "memory");
}

__device__ __forceinline__ uint32_t elect1() {
    uint32_t p;
    asm("{\n\t.reg .pred p;\n\telect.sync _|p, 0xFFFFFFFF;\n\tselp.b32 %0, 1, 0, p;\n\t}"
        : "=r"(p));
    return p;
}

// idesc (kind::f16): dtype=F32(1<<4), a/btype=BF16, N/8<<17, M/16<<24
// M=128,N=128 -> 0x8200490 (formula validated by test_mma's 0x8080490 @ N=32)
#define GIDESC ((1u << 4) | (1u << 7) | (1u << 10) | ((128u / 8) << 17) | ((128u / 16) << 24))

// C tile (128x128) at (bx,by) = A[128,Kd] * B[128,Kd]^T, bf16 hi/lo 3-pass.
__device__ void gemm_tile(const float* __restrict__ A, const float* __restrict__ B,
                          float* __restrict__ C, int N, int Kd, int bx, int by) {
    extern __shared__ uint8_t sm8[];
    const uint32_t sb = smem_u32(sm8);
    const int AHI = 1024, ALO = 1024 + 16384, BHI = 1024 + 32768, BLO = 1024 + 49152;

    const int tid  = threadIdx.x;
    const int wid  = tid >> 5;
    const int lane = tid & 31;

    if (wid == 0)
        asm volatile("tcgen05.alloc.cta_group::1.sync.aligned.shared::cta.b32 [%0], %1;"
                     :: "r"(sb), "r"(128u) : "memory");
    if (tid == 0)
        asm volatile("mbarrier.init.shared.b64 [%0], %1;" :: "r"(sb + 8), "r"(1u) : "memory");
    __syncthreads();
    uint32_t tb;
    asm volatile("ld.shared.b32 %0, [%1];" : "=r"(tb) : "r"(sb));
    if (wid == 0)
        asm volatile("tcgen05.relinquish_alloc_permit.cta_group::1.sync.aligned;");

    const int rr = tid >> 4;           // 0..15
    const int cq = (tid & 15) * 4;     // float col 0,4,..,60
    const float* Abase = A + (size_t)(by * 128) * Kd;
    const float* Bbase = B + (size_t)(bx * 128) * Kd;

    const int nch = Kd / 64;
    for (int kc = 0; kc < nch; kc++) {
        // stage A and B chunk (bf16 hi/lo, SW128)
#pragma unroll
        for (int p = 0; p < 8; p++) {
            int row = p * 16 + rr;
            uint32_t off = row * 128 + cq * 2;
            uint32_t sw = off ^ ((off >> 3) & 0x70);
            {
                float4 v = *(const float4*)(Abase + (size_t)row * Kd + kc * 64 + cq);
                uint32_t h01 = cvt_bf2(v.x, v.y), h23 = cvt_bf2(v.z, v.w);
                float hf0 = __uint_as_float(h01 << 16);
                float hf1 = __uint_as_float(h01 & 0xffff0000u);
                float hf2 = __uint_as_float(h23 << 16);
                float hf3 = __uint_as_float(h23 & 0xffff0000u);
                uint32_t l01 = cvt_bf2(v.x - hf0, v.y - hf1);
                uint32_t l23 = cvt_bf2(v.z - hf2, v.w - hf3);
                *(uint2*)(sm8 + AHI + sw) = make_uint2(h01, h23);
                *(uint2*)(sm8 + ALO + sw) = make_uint2(l01, l23);
            }
            {
                float4 v = *(const float4*)(Bbase + (size_t)row * Kd + kc * 64 + cq);
                uint32_t h01 = cvt_bf2(v.x, v.y), h23 = cvt_bf2(v.z, v.w);
                float hf0 = __uint_as_float(h01 << 16);
                float hf1 = __uint_as_float(h01 & 0xffff0000u);
                float hf2 = __uint_as_float(h23 << 16);
                float hf3 = __uint_as_float(h23 & 0xffff0000u);
                uint32_t l01 = cvt_bf2(v.x - hf0, v.y - hf1);
                uint32_t l23 = cvt_bf2(v.z - hf2, v.w - hf3);
                *(uint2*)(sm8 + BHI + sw) = make_uint2(h01, h23);
                *(uint2*)(sm8 + BLO + sw) = make_uint2(l01, l23);
            }
        }
        asm volatile("fence.proxy.async.shared::cta;" ::: "memory");
        __syncthreads();

        // MMA: 4 k16-steps x 3 passes (hi*hi, hi*lo, lo*hi)
        if (wid == 0 && elect1()) {
            uint64_t dAh = mk_desc(sb + AHI), dAl = mk_desc(sb + ALO);
            uint64_t dBh = mk_desc(sb + BHI), dBl = mk_desc(sb + BLO);
#pragma unroll
            for (int k = 0; k < 4; k++) {
                uint64_t o = (uint64_t)(k * 2);
                mma_f16_ss(tb, dAh + o, dBh + o, GIDESC, !(kc == 0 && k == 0));
                mma_f16_ss(tb, dAh + o, dBl + o, GIDESC, true);
                mma_f16_ss(tb, dAl + o, dBh + o, GIDESC, true);
            }
            asm volatile(
                "tcgen05.commit.cta_group::1.mbarrier::arrive::one.shared::cluster.b64 [%0];"
                :: "r"(sb + 8) : "memory");
        }
        mbar_wait(sb + 8, kc & 1);
        __syncthreads();
    }

    asm volatile("tcgen05.fence::after_thread_sync;" ::: "memory");

    // epilogue: warps 0-3 read D (each warp sees its own 32-lane subpartition)
    if (wid < 4) {
        float* dst0 = C + (size_t)(by * 128 + wid * 32 + lane) * N + bx * 128;
#pragma unroll
        for (int cb = 0; cb < 4; cb++) {
            uint32_t r[32];
            asm volatile(
                "tcgen05.ld.sync.aligned.32x32b.x32.b32 "
                "{%0, %1, %2, %3, %4, %5, %6, %7, "
                " %8, %9, %10, %11, %12, %13, %14, %15, "
                " %16, %17, %18, %19, %20, %21, %22, %23, "
                " %24, %25, %26, %27, %28, %29, %30, %31}, [%32];"
                : "=r"(r[0]),  "=r"(r[1]),  "=r"(r[2]),  "=r"(r[3]),
                  "=r"(r[4]),  "=r"(r[5]),  "=r"(r[6]),  "=r"(r[7]),
                  "=r"(r[8]),  "=r"(r[9]),  "=r"(r[10]), "=r"(r[11]),
                  "=r"(r[12]), "=r"(r[13]), "=r"(r[14]), "=r"(r[15]),
                  "=r"(r[16]), "=r"(r[17]), "=r"(r[18]), "=r"(r[19]),
                  "=r"(r[20]), "=r"(r[21]), "=r"(r[22]), "=r"(r[23]),
                  "=r"(r[24]), "=r"(r[25]), "=r"(r[26]), "=r"(r[27]),
                  "=r"(r[28]), "=r"(r[29]), "=r"(r[30]), "=r"(r[31])
                : "r"(tb + cb * 32));
            asm volatile("tcgen05.wait::ld.sync.aligned;" ::: "memory");
#pragma unroll
            for (int i = 0; i < 8; i++) {
                float4 o = {__uint_as_float(r[i * 4 + 0]), __uint_as_float(r[i * 4 + 1]),
                            __uint_as_float(r[i * 4 + 2]), __uint_as_float(r[i * 4 + 3])};
                *(float4*)(dst0 + cb * 32 + i * 4) = o;
            }
        }
    }

    __syncthreads();
    if (tid == 0)
        asm volatile("mbarrier.inval.shared.b64 [%0];" :: "r"(sb + 8) : "memory");
    __syncthreads();
    if (wid == 0)
        asm volatile("tcgen05.dealloc.cta_group::1.sync.aligned.b32 %0, %1;"
                     :: "r"(tb), "r"(128u));
}

#else
// ===========================================================================
// Fallback path (generic compute_103 PTX pass; R7-measured HMMA GEMM,
// double-buffered, BM=BN=128, BK=16, warp tile 64x32, dynamic smem)
// ===========================================================================
__device__ void gemm_tile(const float* __restrict__ A, const float* __restrict__ B,
                          float* __restrict__ C, int N, int Kd, int bx, int by) {
    extern __shared__ uint8_t sm8[];
    uint32_t* As = (uint32_t*)sm8;                       // 2 x [128*SMS]
    uint32_t* Bs = (uint32_t*)sm8 + 2 * 128 * SMS;       // 2 x [128*SMS]

    const int tid  = threadIdx.x;
    const int wid  = tid >> 5;
    const int lane = tid & 31;
    const int wm   = (wid & 1) * 64;
    const int wn   = (wid >> 1) * 32;
    const int g    = lane >> 2;
    const int c    = lane & 3;

    const int sr = tid >> 2;
    const int sc = (tid & 3) * 4;
    const float* Ap = A + (size_t)(by * 128 + sr) * Kd + sc;
    const float* Bp = B + (size_t)(bx * 128 + sr) * Kd + sc;

    float acc[4][4][4];
#pragma unroll
    for (int i = 0; i < 4; i++)
#pragma unroll
        for (int j = 0; j < 4; j++)
#pragma unroll
            for (int k = 0; k < 4; k++) acc[i][j][k] = 0.f;

    float4 ra0 = *(const float4*)(Ap);
    float4 ra1 = *(const float4*)(Ap + (size_t)64 * Kd);
    float4 rb0 = *(const float4*)(Bp);
    float4 rb1 = *(const float4*)(Bp + (size_t)64 * Kd);

    {
        uint4 u;
        u.x = f2tf(ra0.x); u.y = f2tf(ra0.y); u.z = f2tf(ra0.z); u.w = f2tf(ra0.w);
        *(uint4*)&As[sr * SMS + sc] = u;
        u.x = f2tf(ra1.x); u.y = f2tf(ra1.y); u.z = f2tf(ra1.z); u.w = f2tf(ra1.w);
        *(uint4*)&As[(sr + 64) * SMS + sc] = u;
        u.x = f2tf(rb0.x); u.y = f2tf(rb0.y); u.z = f2tf(rb0.z); u.w = f2tf(rb0.w);
        *(uint4*)&Bs[sr * SMS + sc] = u;
        u.x = f2tf(rb1.x); u.y = f2tf(rb1.y); u.z = f2tf(rb1.z); u.w = f2tf(rb1.w);
        *(uint4*)&Bs[(sr + 64) * SMS + sc] = u;
    }
    __syncthreads();

    int cur = 0;
    for (int k0 = 0; k0 < Kd; k0 += 16) {
        const bool has_next = (k0 + 16 < Kd);
        if (has_next) {
            ra0 = *(const float4*)(Ap + k0 + 16);
            ra1 = *(const float4*)(Ap + (size_t)64 * Kd + k0 + 16);
            rb0 = *(const float4*)(Bp + k0 + 16);
            rb1 = *(const float4*)(Bp + (size_t)64 * Kd + k0 + 16);
        }

        const uint32_t* Ab = As + cur * (128 * SMS);
        const uint32_t* Bb = Bs + cur * (128 * SMS);
#pragma unroll
        for (int kk = 0; kk < 16; kk += 8) {
            uint32_t af[4][4], bf[4][2];
#pragma unroll
            for (int mt = 0; mt < 4; mt++) {
                int r0 = wm + mt * 16 + g;
                af[mt][0] = Ab[r0 * SMS + kk + c];
                af[mt][1] = Ab[(r0 + 8) * SMS + kk + c];
                af[mt][2] = Ab[r0 * SMS + kk + c + 4];
                af[mt][3] = Ab[(r0 + 8) * SMS + kk + c + 4];
            }
#pragma unroll
            for (int nt = 0; nt < 4; nt++) {
                int n0 = wn + nt * 8 + g;
                bf[nt][0] = Bb[n0 * SMS + kk + c];
                bf[nt][1] = Bb[n0 * SMS + kk + c + 4];
            }
#pragma unroll
            for (int mt = 0; mt < 4; mt++)
#pragma unroll
                for (int nt = 0; nt < 4; nt++)
                    mma_tf32(acc[mt][nt], af[mt], bf[nt]);
        }

        if (has_next) {
            uint32_t* An = As + (cur ^ 1) * (128 * SMS);
            uint32_t* Bn = Bs + (cur ^ 1) * (128 * SMS);
            uint4 u;
            u.x = f2tf(ra0.x); u.y = f2tf(ra0.y); u.z = f2tf(ra0.z); u.w = f2tf(ra0.w);
            *(uint4*)&An[sr * SMS + sc] = u;
            u.x = f2tf(ra1.x); u.y = f2tf(ra1.y); u.z = f2tf(ra1.z); u.w = f2tf(ra1.w);
            *(uint4*)&An[(sr + 64) * SMS + sc] = u;
            u.x = f2tf(rb0.x); u.y = f2tf(rb0.y); u.z = f2tf(rb0.z); u.w = f2tf(rb0.w);
            *(uint4*)&Bn[sr * SMS + sc] = u;
            u.x = f2tf(rb1.x); u.y = f2tf(rb1.y); u.z = f2tf(rb1.z); u.w = f2tf(rb1.w);
            *(uint4*)&Bn[(sr + 64) * SMS + sc] = u;
            __syncthreads();
            cur ^= 1;
        }
    }

#pragma unroll
    for (int mt = 0; mt < 4; mt++) {
#pragma unroll
        for (int nt = 0; nt < 4; nt++) {
            int row = by * 128 + wm + mt * 16 + g;
            int col = bx * 128 + wn + nt * 8 + c * 2;
            float2 v0 = {acc[mt][nt][0], acc[mt][nt][1]};
            float2 v1 = {acc[mt][nt][2], acc[mt][nt][3]};
            *(float2*)(C + (size_t)row * N + col)       = v0;
            *(float2*)(C + (size_t)(row + 8) * N + col) = v1;
        }
    }
}
#endif  // TC5

// Q/K/V projections, flat grid: [0,512) Q, [512,640) K, [640,768) V
__global__ void __launch_bounds__(256) gemm_qkv_tc(const float* __restrict__ X,
                                                   const float* __restrict__ Wq,
                                                   const float* __restrict__ Wk,
                                                   const float* __restrict__ Wv,
                                                   float* __restrict__ Q,
                                                   float* __restrict__ K,
                                                   float* __restrict__ V) {
    int bid = blockIdx.x;
    if (bid < 512)      gemm_tile(X, Wq, Q, QDIM,  HID, bid % 32, bid / 32);
    else if (bid < 640) { int t = bid - 512; gemm_tile(X, Wk, K, KVDIM, HID, t % 8, t / 8); }
    else                { int t = bid - 640; gemm_tile(X, Wv, V, KVDIM, HID, t % 8, t / 8); }
}

// Output projection: grid 320 = 20 x 16
__global__ void __launch_bounds__(256) gemm_o_tc(const float* __restrict__ AO,
                                                 const float* __restrict__ Wo,
                                                 float* __restrict__ out) {
    int bid = blockIdx.x;
    gemm_tile(AO, Wo, out, HID, QDIM, bid % 20, bid / 20);
}

// ===========================================================================
// Merged per-head RMSNorm + RoPE over BOTH Q and K, in-place.
// ===========================================================================
__global__ void rms_rope_all(float* __restrict__ Qx, float* __restrict__ Kx,
                             const float* __restrict__ qw, const float* __restrict__ kw,
                             const float* __restrict__ cosp, const float* __restrict__ sinp) {
    const int NQ = S_LEN * NH;
    int warp = (blockIdx.x * blockDim.x + threadIdx.x) >> 5;
    int lane = threadIdx.x & 31;

    float* p;
    const float* w;
    int s;
    if (warp < NQ) {
        p = Qx + (size_t)warp * HD;
        w = qw;
        s = warp / NH;
    } else {
        int t = warp - NQ;
        p = Kx + (size_t)t * HD;
        w = kw;
        s = t / NKV;
    }

    float4 x = *(float4*)(p + lane * 4);

    float ss = x.x * x.x + x.y * x.y + x.z * x.z + x.w * x.w;
#pragma unroll
    for (int o = 16; o; o >>= 1) ss += __shfl_xor_sync(0xffffffffu, ss, o);
    float r = rsqrtf(ss * (1.0f / HD) + 1e-6f);

    float4 wv = *(const float4*)(w + lane * 4);
    x.x *= r * wv.x; x.y *= r * wv.y; x.z *= r * wv.z; x.w *= r * wv.w;

    float4 rot;
    rot.x = __shfl_xor_sync(0xffffffffu, x.x, 16);
    rot.y = __shfl_xor_sync(0xffffffffu, x.y, 16);
    rot.z = __shfl_xor_sync(0xffffffffu, x.z, 16);
    rot.w = __shfl_xor_sync(0xffffffffu, x.w, 16);
    float sgn = (lane < 16) ? -1.f : 1.f;

    float4 cv = *(const float4*)(cosp + (size_t)s * HD + lane * 4);
    float4 sv = *(const float4*)(sinp + (size_t)s * HD + lane * 4);

    float4 o;
    o.x = x.x * cv.x + sgn * rot.x * sv.x;
    o.y = x.y * cv.y + sgn * rot.y * sv.y;
    o.z = x.z * cv.z + sgn * rot.z * sv.z;
    o.w = x.w * cv.w + sgn * rot.w * sv.w;
    *(float4*)(p + lane * 4) = o;
}

// ===========================================================================
// Tensor-core causal GQA flash attention (R10 best-measured version).
// TF32 HMMA, 256 threads / 8 warps, 128 q rows; Q hi/lo precomputed in smem.
// ===========================================================================
#define QS_STRIDE 132
#define VS_STRIDE 136

__global__ void __launch_bounds__(256, 1) flash_tc(const float* __restrict__ Q,
                                                   const float* __restrict__ K,
                                                   const float* __restrict__ V,
                                                   float* __restrict__ O) {
    extern __shared__ uint32_t smf[];
    uint32_t* Qhi = smf;                                // [128][132] tf32
    uint32_t* Qlo = smf + 128 * QS_STRIDE;              // [128][132] tf32
    uint32_t* Ks  = smf + 2 * 128 * QS_STRIDE;          // [64][132] tf32
    uint32_t* Vs  = Ks + 64 * QS_STRIDE;                // [64][136] tf32

    const int tid  = threadIdx.x;
    const int w    = tid >> 5;
    const int lane = tid & 31;
    const int g    = lane >> 2;
    const int c    = lane & 3;
    const int h    = blockIdx.y;
    const int kvh  = h >> 2;
    const int base = blockIdx.x * 128;
    const int m0   = w * 16;
    const float scale = 0.08838834764831845f;  // 1/sqrt(128)
    const float FM = 12.0f;

    // stage Q tile with hi/lo split (once per block)
    {
        int r = tid >> 1, half = (tid & 1) * 64;
        const float* src = Q + (size_t)(base + r) * QDIM + h * HD + half;
        uint32_t* dh = Qhi + r * QS_STRIDE + half;
        uint32_t* dl = Qlo + r * QS_STRIDE + half;
#pragma unroll
        for (int i = 0; i < 16; i++) {
            float4 q4 = *(const float4*)(src + i * 4);
            uint4 hv, lv;
            hv.x = f2tf(q4.x); lv.x = f2tf(q4.x - __uint_as_float(hv.x));
            hv.y = f2tf(q4.y); lv.y = f2tf(q4.y - __uint_as_float(hv.y));
            hv.z = f2tf(q4.z); lv.z = f2tf(q4.z - __uint_as_float(hv.z));
            hv.w = f2tf(q4.w); lv.w = f2tf(q4.w - __uint_as_float(hv.w));
            *(uint4*)(dh + i * 4) = hv;
            *(uint4*)(dl + i * 4) = lv;
        }
    }

    float oacc[16][4];
#pragma unroll
    for (int i = 0; i < 16; i++) {
        oacc[i][0] = 0.f; oacc[i][1] = 0.f; oacc[i][2] = 0.f; oacc[i][3] = 0.f;
    }
    float lr0 = 0.f, lr1 = 0.f;

    const int row0 = base + m0 + g;
    const int row1 = row0 + 8;
    const int wmax = base + m0 + 15;

    for (int kb = 0; kb <= base + 127; kb += 64) {
        __syncthreads();
        {
            int r = tid >> 2, qtr = (tid & 3) * 32;
            const float* ks = K + (size_t)(kb + r) * KVDIM + kvh * HD + qtr;
            const float* vs = V + (size_t)(kb + r) * KVDIM + kvh * HD + qtr;
            uint32_t* kd = Ks + r * QS_STRIDE + qtr;
            uint32_t* vd = Vs + r * VS_STRIDE + qtr;
#pragma unroll
            for (int i = 0; i < 8; i++) {
                float4 k4 = *(const float4*)(ks + i * 4);
                uint4 ku = {f2tf(k4.x), f2tf(k4.y), f2tf(k4.z), f2tf(k4.w)};
                *(uint4*)(kd + i * 4) = ku;
                float4 v4 = *(const float4*)(vs + i * 4);
                uint4 vu = {f2tf(v4.x), f2tf(v4.y), f2tf(v4.z), f2tf(v4.w)};
                *(uint4*)(vd + i * 4) = vu;
            }
        }
        __syncthreads();

        if (kb > wmax) continue;

        float sacc[8][4];
#pragma unroll
        for (int nt = 0; nt < 8; nt++) {
            sacc[nt][0] = 0.f; sacc[nt][1] = 0.f; sacc[nt][2] = 0.f; sacc[nt][3] = 0.f;
        }
#pragma unroll
        for (int ks8 = 0; ks8 < 16; ks8++) {
            const int kk = ks8 * 8;
            uint32_t ahi[4], alo[4];
            ahi[0] = Qhi[(m0 + g) * QS_STRIDE + kk + c];
            ahi[1] = Qhi[(m0 + 8 + g) * QS_STRIDE + kk + c];
            ahi[2] = Qhi[(m0 + g) * QS_STRIDE + kk + c + 4];
            ahi[3] = Qhi[(m0 + 8 + g) * QS_STRIDE + kk + c + 4];
            alo[0] = Qlo[(m0 + g) * QS_STRIDE + kk + c];
            alo[1] = Qlo[(m0 + 8 + g) * QS_STRIDE + kk + c];
            alo[2] = Qlo[(m0 + g) * QS_STRIDE + kk + c + 4];
            alo[3] = Qlo[(m0 + 8 + g) * QS_STRIDE + kk + c + 4];
#pragma unroll
            for (int nt = 0; nt < 8; nt++) {
                uint32_t b[2];
                b[0] = Ks[(nt * 8 + g) * QS_STRIDE + kk + c];
                b[1] = Ks[(nt * 8 + g) * QS_STRIDE + kk + c + 4];
                mma_tf32(sacc[nt], alo, b);
                mma_tf32(sacc[nt], ahi, b);
            }
        }

        uint32_t pb[8][4];
#pragma unroll
        for (int nt = 0; nt < 8; nt++) {
            int colb = kb + nt * 8 + 2 * c;
            float p0 = (colb     <= row0) ? __expf(fmaf(sacc[nt][0], scale, -FM)) : 0.f;
            float p1 = (colb + 1 <= row0) ? __expf(fmaf(sacc[nt][1], scale, -FM)) : 0.f;
            float p2 = (colb     <= row1) ? __expf(fmaf(sacc[nt][2], scale, -FM)) : 0.f;
            float p3 = (colb + 1 <= row1) ? __expf(fmaf(sacc[nt][3], scale, -FM)) : 0.f;
            lr0 += p0 + p1;
            lr1 += p2 + p3;
            pb[nt][0] = f2tf(p0); pb[nt][1] = f2tf(p1);
            pb[nt][2] = f2tf(p2); pb[nt][3] = f2tf(p3);
        }

        const int src0 = (lane & ~3) | (c >> 1);
        const int src1 = src0 + 2;
#pragma unroll
        for (int kt = 0; kt < 8; kt++) {
            uint32_t x0 = __shfl_sync(0xffffffffu, pb[kt][0], src0);
            uint32_t x1 = __shfl_sync(0xffffffffu, pb[kt][1], src0);
            uint32_t x2 = __shfl_sync(0xffffffffu, pb[kt][2], src0);
            uint32_t x3 = __shfl_sync(0xffffffffu, pb[kt][3], src0);
            uint32_t y0 = __shfl_sync(0xffffffffu, pb[kt][0], src1);
            uint32_t y1 = __shfl_sync(0xffffffffu, pb[kt][1], src1);
            uint32_t y2 = __shfl_sync(0xffffffffu, pb[kt][2], src1);
            uint32_t y3 = __shfl_sync(0xffffffffu, pb[kt][3], src1);
            uint32_t a[4];
            a[0] = (c & 1) ? x1 : x0;
            a[1] = (c & 1) ? x3 : x2;
            a[2] = (c & 1) ? y1 : y0;
            a[3] = (c & 1) ? y3 : y2;
#pragma unroll
            for (int nt = 0; nt < 16; nt++) {
                uint32_t b[2];
                b[0] = Vs[(kt * 8 + c) * VS_STRIDE + nt * 8 + g];
                b[1] = Vs[(kt * 8 + c + 4) * VS_STRIDE + nt * 8 + g];
                mma_tf32(oacc[nt], a, b);
            }
        }
    }

    lr0 += __shfl_xor_sync(0xffffffffu, lr0, 1);
    lr0 += __shfl_xor_sync(0xffffffffu, lr0, 2);
    lr1 += __shfl_xor_sync(0xffffffffu, lr1, 1);
    lr1 += __shfl_xor_sync(0xffffffffu, lr1, 2);
    float inv0 = 1.f / lr0;
    float inv1 = 1.f / lr1;

    float* o0 = O + (size_t)row0 * QDIM + h * HD;
    float* o1 = O + (size_t)row1 * QDIM + h * HD;
#pragma unroll
    for (int nt = 0; nt < 16; nt++) {
        int col = nt * 8 + 2 * c;
        float2 v0 = {oacc[nt][0] * inv0, oacc[nt][1] * inv0};
        float2 v1 = {oacc[nt][2] * inv1, oacc[nt][3] * inv1};
        *(float2*)(o0 + col) = v0;
        *(float2*)(o1 + col) = v1;
    }
}

// ===========================================================================
extern "C" void kernel_launch(void* const* d_in, const int* in_sizes, int n_in,
                              void* d_out, int out_size) {
    const float* X    = (const float*)d_in[0];
    const float* cosp = (const float*)d_in[1];
    const float* sinp = (const float*)d_in[2];
    const float* Wq   = (const float*)d_in[3];
    const float* Wk   = (const float*)d_in[4];
    const float* Wv   = (const float*)d_in[5];
    const float* Wo   = (const float*)d_in[6];
    const float* qw   = (const float*)d_in[7];
    const float* kw   = (const float*)d_in[8];
    float* out = (float*)d_out;

    float *Q, *K, *V, *AO;
    cudaGetSymbolAddress((void**)&Q,  g_Q);
    cudaGetSymbolAddress((void**)&K,  g_K);
    cudaGetSymbolAddress((void**)&V,  g_V);
    cudaGetSymbolAddress((void**)&AO, g_AO);

    cudaFuncSetAttribute(gemm_qkv_tc, cudaFuncAttributeMaxDynamicSharedMemorySize, GSMEM);
    cudaFuncSetAttribute(gemm_o_tc,   cudaFuncAttributeMaxDynamicSharedMemorySize, GSMEM);

    // Q + K + V projections
    gemm_qkv_tc<<<768, 256, GSMEM>>>(X, Wq, Wk, Wv, Q, K, V);

    // RMSNorm + RoPE on Q and K
    {
        int nwarps = S_LEN * NH + S_LEN * NKV;
        rms_rope_all<<<nwarps / 8, 256>>>(Q, K, qw, kw, cosp, sinp);
    }

    // Flash attention (TF32 HMMA, R10 config)
    int fsmem = (2 * 128 * QS_STRIDE + 64 * QS_STRIDE + 64 * VS_STRIDE) * 4;  // ~204KB
    cudaFuncSetAttribute(flash_tc, cudaFuncAttributeMaxDynamicSharedMemorySize, fsmem);
    flash_tc<<<dim3(S_LEN / 128, NH), 256, fsmem>>>(Q, K, V, AO);

    // Output projection
    gemm_o_tc<<<320, 256, GSMEM>>>(AO, Wo, out);
}